// round 17
// baseline (speedup 1.0000x reference)
#include <cuda_runtime.h>
#include <math.h>

#define SOM_DIM   512
#define SOM_MN    65536            // 256*256 rows
#define ROW_SPLIT 20480            // rows >= this tagged evict-last in L2

// Pass 1: 2 rows per warp, 8 warps/block.
#define P1_WARPS 8
#define P1_ROWS_PER_BLK (P1_WARPS * 2)            // 16
#define P1_BLOCKS (SOM_MN / P1_ROWS_PER_BLK)      // 4096

// Pass 2: 1 row per warp, 8 warps/block (R14 champion config).
#define P2_ROWS_PER_BLK 8
#define P2_BLOCKS (SOM_MN / P2_ROWS_PER_BLK)      // 8192

__device__ unsigned long long g_key = 0xFFFFFFFFFFFFFFFFULL;
__device__ unsigned int g_ticket2 = 0;

// ---- L2 cache-policy helpers ------------------------------------------------
__device__ __forceinline__ unsigned long long pol_evict_last() {
    unsigned long long p;
    asm("createpolicy.fractional.L2::evict_last.b64 %0, 1.0;" : "=l"(p));
    return p;
}
__device__ __forceinline__ unsigned long long pol_evict_first() {
    unsigned long long p;
    asm("createpolicy.fractional.L2::evict_first.b64 %0, 1.0;" : "=l"(p));
    return p;
}

// 256-bit global load (sm_103a LDG.256) with L2 policy. v = 8 floats.
struct f8 { float v[8]; };
__device__ __forceinline__ f8 ldg_v8_pol(const float* p, unsigned long long pol) {
    f8 r;
    asm("ld.global.L2::cache_hint.v8.b32 {%0,%1,%2,%3,%4,%5,%6,%7}, [%8], %9;"
        : "=f"(r.v[0]), "=f"(r.v[1]), "=f"(r.v[2]), "=f"(r.v[3]),
          "=f"(r.v[4]), "=f"(r.v[5]), "=f"(r.v[6]), "=f"(r.v[7])
        : "l"(p), "l"(pol));
    return r;
}
__device__ __forceinline__ f8 ldg_v8(const float* p) {
    f8 r;
    asm("ld.global.nc.v8.b32 {%0,%1,%2,%3,%4,%5,%6,%7}, [%8];"
        : "=f"(r.v[0]), "=f"(r.v[1]), "=f"(r.v[2]), "=f"(r.v[3]),
          "=f"(r.v[4]), "=f"(r.v[5]), "=f"(r.v[6]), "=f"(r.v[7])
        : "l"(p));
    return r;
}
__device__ __forceinline__ void stg_cs_v4(float* p, float a, float b, float c2, float d) {
    asm volatile("st.global.cs.v4.f32 [%0], {%1,%2,%3,%4};"
                 :: "l"(p), "f"(a), "f"(b), "f"(c2), "f"(d) : "memory");
}

// ---------------------------------------------------------------------------
// Pass 1: squared distance per row (argmin of sqrt == argmin of sum).
// 2 rows per warp, ASCENDING; 256-bit W loads (2 per row per lane).
// Tail rows evict-last, head evict-first. Block min -> atomicMin(g_key),
// then PDL trigger immediately.
// ---------------------------------------------------------------------------
__global__ __launch_bounds__(256) void som_dist_kernel(
    const float* __restrict__ x, const float* __restrict__ w)
{
    __shared__ unsigned long long s_keys[P1_WARPS];
    const int lane = threadIdx.x & 31;
    const int warp = threadIdx.x >> 5;
    const int row0 = blockIdx.x * P1_ROWS_PER_BLK + warp * 2;

    const unsigned long long pol = (row0 >= ROW_SPLIT) ? pol_evict_last()
                                                       : pol_evict_first();

    const float* wr0 = w + (size_t)row0 * SOM_DIM;
    const float* wr1 = wr0 + SOM_DIM;

    // 256-bit front-batched loads: lane covers 8 floats per load, 2 loads/row.
    f8 wv0a = ldg_v8_pol(wr0 + lane * 8, pol);
    f8 wv0b = ldg_v8_pol(wr0 + 256 + lane * 8, pol);
    f8 wv1a = ldg_v8_pol(wr1 + lane * 8, pol);
    f8 wv1b = ldg_v8_pol(wr1 + 256 + lane * 8, pol);
    f8 xa   = ldg_v8(x + lane * 8);
    f8 xb   = ldg_v8(x + 256 + lane * 8);

    float a0 = 0.f, a1 = 0.f;
#pragma unroll
    for (int i = 0; i < 8; i++) {
        float d;
        d = xa.v[i] - wv0a.v[i] + 1e-6f; a0 += d * d;
        d = xb.v[i] - wv0b.v[i] + 1e-6f; a0 += d * d;
        d = xa.v[i] - wv1a.v[i] + 1e-6f; a1 += d * d;
        d = xb.v[i] - wv1b.v[i] + 1e-6f; a1 += d * d;
    }
#pragma unroll
    for (int o = 16; o > 0; o >>= 1) {
        a0 += __shfl_xor_sync(0xFFFFFFFFu, a0, o);
        a1 += __shfl_xor_sync(0xFFFFFFFFu, a1, o);
    }

    if (lane == 0) {
        // dist >= 0 so fp32 bits are order-preserving; smaller row wins ties.
        unsigned long long k0 =
            ((unsigned long long)__float_as_uint(a0) << 32) | (unsigned)row0;
        unsigned long long k1 =
            ((unsigned long long)__float_as_uint(a1) << 32) | (unsigned)(row0 + 1);
        s_keys[warp] = min(k0, k1);
    }
    __syncthreads();
    if (threadIdx.x == 0) {
        unsigned long long k = s_keys[0];
#pragma unroll
        for (int i = 1; i < P1_WARPS; i++)
            k = min(k, s_keys[i]);
        atomicMin(&g_key, k);
        __threadfence();
    }
    __syncthreads();
    cudaTriggerProgrammaticLaunchCompletion();
}

// ---------------------------------------------------------------------------
// Pass 2 (PDL secondary): DESCENDING rows (boustrophedon with p1 across
// replays — best measured). 256-bit W/x loads front-batched before the
// grid sync; scalars derived per-thread in fp32; loc is exact meshgrid
// arithmetic. Tail evict-last, head evict-first, out stored .cs (v4).
// Last block resets g_key for the next graph replay.
// ---------------------------------------------------------------------------
__global__ __launch_bounds__(256) void som_update_kernel(
    const float* __restrict__ x, const float* __restrict__ w,
    const int* __restrict__ it_p, float* __restrict__ out, int has_idx_tail)
{
    const int lane = threadIdx.x & 31;
    const int warp = threadIdx.x >> 5;
    const int row  = (SOM_MN - 1) - (blockIdx.x * P2_ROWS_PER_BLK + warp);

    const unsigned long long pol = (row >= ROW_SPLIT) ? pol_evict_last()
                                                      : pol_evict_first();

    const float* wr = w + (size_t)row * SOM_DIM;
    float* orow = out + (size_t)row * SOM_DIM;

    // ---- p1-independent prework: issue all streaming loads now ----
    f8 wa = ldg_v8_pol(wr + lane * 8, pol);
    f8 wb = ldg_v8_pol(wr + 256 + lane * 8, pol);
    f8 xa = ldg_v8(x + lane * 8);
    f8 xb = ldg_v8(x + 256 + lane * 8);
    const int it = *it_p;                         // p1-independent scalar

    // ---- wait for pass 1 grid completion (g_key final) ----
    cudaGridDependencySynchronize();

    const int bidx = (int)(g_key & 0xFFFFFFFFu);

    // Iteration scalars, fp32 (hidden under the in-flight loads).
    const float decay = expf(-(float)it / 2000.0f);   // N_ITER
    const float rate  = 0.5f * decay;                 // ALPHA * decay
    const float sig   = 128.0f * decay;               // SIGMA * decay
    const float inv2s2 = 1.0f / (2.0f * sig * sig);

    // locations are exact meshgrid ints: loc[r] = (r>>8, r&255) in fp32.
    const float d0 = (float)(bidx >> 8)  - (float)(row >> 8)  + 1e-6f;
    const float d1 = (float)(bidx & 255) - (float)(row & 255) + 1e-6f;
    const float ld = sqrtf(d0 * d0 + d1 * d1);        // match sqrt-then-square
    const float c  = rate * expf(-(ld * ld) * inv2s2);

    float oa[8], ob[8];
#pragma unroll
    for (int i = 0; i < 8; i++) {
        oa[i] = wa.v[i] + c * (xa.v[i] - wa.v[i]);
        ob[i] = wb.v[i] + c * (xb.v[i] - wb.v[i]);
    }
    stg_cs_v4(orow + lane * 8,           oa[0], oa[1], oa[2], oa[3]);
    stg_cs_v4(orow + lane * 8 + 4,       oa[4], oa[5], oa[6], oa[7]);
    stg_cs_v4(orow + 256 + lane * 8,     ob[0], ob[1], ob[2], ob[3]);
    stg_cs_v4(orow + 256 + lane * 8 + 4, ob[4], ob[5], ob[6], ob[7]);

    if (has_idx_tail && blockIdx.x == 0 && threadIdx.x == 0)
        out[(size_t)SOM_MN * SOM_DIM] = (float)bidx;

    // Last finishing block resets g_key for the next graph replay.
    __syncthreads();
    if (threadIdx.x == 0) {
        const unsigned t = atomicAdd(&g_ticket2, 1u);
        if (t == (unsigned)(gridDim.x - 1)) {
            g_ticket2 = 0u;
            g_key = 0xFFFFFFFFFFFFFFFFULL;
            __threadfence();
        }
    }
}

extern "C" void kernel_launch(void* const* d_in, const int* in_sizes, int n_in,
                              void* d_out, int out_size)
{
    const float* x   = (const float*)d_in[0];   // (512,)
    const float* w   = (const float*)d_in[1];   // (65536, 512)
    const int*   it  = (const int*)d_in[3];     // scalar
    float* out = (float*)d_out;

    const int has_tail = (out_size > SOM_MN * SOM_DIM) ? 1 : 0;

    som_dist_kernel<<<P1_BLOCKS, 256>>>(x, w);

    // Pass 2 as a PDL secondary: may begin while pass 1 drains.
    cudaLaunchConfig_t cfg = {};
    cfg.gridDim  = dim3(P2_BLOCKS, 1, 1);
    cfg.blockDim = dim3(256, 1, 1);
    cudaLaunchAttribute attrs[1];
    attrs[0].id = cudaLaunchAttributeProgrammaticStreamSerialization;
    attrs[0].val.programmaticStreamSerializationAllowed = 1;
    cfg.attrs = attrs;
    cfg.numAttrs = 1;
    cudaLaunchKernelEx(&cfg, som_update_kernel, x, w, it, out, has_tail);
}